// round 14
// baseline (speedup 1.0000x reference)
#include <cuda_runtime.h>
#include <cuda_fp16.h>

// Problem constants
#define VSZ   30000
#define OC    128
#define KW    5
#define BATCH 32

constexpr int L    = 2560;          // 40*64 flattened token positions per batch
constexpr int LOUT = L - KW + 1;    // 2556
constexpr int CW   = VSZ * KW;      // 150000 columns (v*5+w)
constexpr int NSUB = 128;           // sub-chunks of the l-range
constexpr int SUBL = 20;            // 128*20 = 2560 >= LOUT

// Scratch: transposed fp16 table, 640B per v, PACKED layout (38.4 MB):
//   per v: 320 uints. uints [4g..4g+3] (g = oc-quad 0..31) = w0 x quad g (2
//   uints) then w1 x quad g; uints [128+4g..] = w2,w3; uints [256+p] = w4,
//   ocpair p. Lets conv fetch a token with 2 LDG.128 + 1 LDG.64.
__device__ __align__(16) __half g_Kt[(size_t)VSZ * KW * OC];
// Per-warp partial maxima: [b][sub][oc]
__device__ float g_partial[BATCH][NSUB][OC];

// ---------------------------------------------------------------------------
// Kernel 1: transpose + fp32->fp16 convert (R8 structure; write-out permuted
// into the packed layout above).
// K is (128 x 150000), row = oc, col = v*5+w.
// Block = 64 columns x 128 oc rows, 256 threads, 4 passes; float4 loads.
// ---------------------------------------------------------------------------
__global__ void __launch_bounds__(256) transpose_kernel(const float* __restrict__ src) {
    __shared__ unsigned tile[64][65];         // [col-local][oc-pair 0..63]
    const int t     = threadIdx.x;
    const int rp0   = t >> 4;                 // 0..15
    const int c4    = (t & 15) * 4;           // column group within tile
    const int cbase = blockIdx.x * 64;
    const int c     = cbase + c4;
    const bool cok  = (c + 3 < CW);           // whole float4 in range (CW%4==0)

    #pragma unroll
    for (int i = 0; i < 4; i++) {
        const int RP = rp0 + 16 * i;          // rowpair 0..63 -> rows 2RP, 2RP+1
        if (cok) {
            const float4 fa = __ldcs(reinterpret_cast<const float4*>(
                                  src + (size_t)(2 * RP)     * CW + c));
            const float4 fb = __ldcs(reinterpret_cast<const float4*>(
                                  src + (size_t)(2 * RP + 1) * CW + c));
            half2 h0 = __floats2half2_rn(fa.x, fb.x);
            half2 h1 = __floats2half2_rn(fa.y, fb.y);
            half2 h2 = __floats2half2_rn(fa.z, fb.z);
            half2 h3 = __floats2half2_rn(fa.w, fb.w);
            tile[c4 + 0][RP] = *reinterpret_cast<unsigned*>(&h0);
            tile[c4 + 1][RP] = *reinterpret_cast<unsigned*>(&h1);
            tile[c4 + 2][RP] = *reinterpret_cast<unsigned*>(&h2);
            tile[c4 + 3][RP] = *reinterpret_cast<unsigned*>(&h3);
        }
    }
    __syncthreads();

    // Write out, permuted into packed layout.
    // colu = oc-pair p (0..63). For column vw = v*5+w:
    //   w<4 : u = (w/2)*128 + (p/2)*4 + (w%2)*2 + (p%2)
    //   w==4: u = 256 + p
    unsigned* __restrict__ KtU = reinterpret_cast<unsigned*>(g_Kt);
    const int colu   = t & 63;
    const int rowsel = t >> 6;                // 0..3
    #pragma unroll
    for (int i = 0; i < 16; i++) {
        int row = rowsel + i * 4;             // col-local 0..63
        int vw  = cbase + row;
        if (vw < CW) {
            int v = vw / 5;
            int w = vw - v * 5;
            int u = (w < 4)
                  ? ((w >> 1) * 128 + ((colu >> 1) << 2) + ((w & 1) << 1) + (colu & 1))
                  : (256 + colu);
            KtU[(size_t)v * 320 + u] = tile[row][colu];
        }
    }
}

// ---------------------------------------------------------------------------
// Kernel 2: gather + sliding-window conv + relu-max, PACKED-LAYOUT loads.
// grid = (NSUB/4, BATCH), 128-thr blocks (R10 winner granularity); one warp
// per sub-chunk, lane l owns oc quad 4l..4l+3 for ALL w.
// Per token: 2x LDG.128 (512B dense each) + 1x LDG.64 (256B) = 3 requests
// (was 5). Sector traffic identical; ring code unchanged.
// Ring-slot reset MUST be unconditional (boundary-pollution flush, see R3).
// ---------------------------------------------------------------------------
__device__ __forceinline__ void addh4(float4& a, const uint2 v) {
    const half2 h0 = *reinterpret_cast<const half2*>(&v.x);
    const half2 h1 = *reinterpret_cast<const half2*>(&v.y);
    float2 f0 = __half22float2(h0);
    float2 f1 = __half22float2(h1);
    a.x += f0.x; a.y += f0.y; a.z += f1.x; a.w += f1.y;
}
__device__ __forceinline__ void max4(float4& a, const float4 b) {
    a.x = fmaxf(a.x, b.x); a.y = fmaxf(a.y, b.y);
    a.z = fmaxf(a.z, b.z); a.w = fmaxf(a.w, b.w);
}

__global__ void __launch_bounds__(128) conv_kernel(const int* __restrict__ tokens) {
    const int b    = blockIdx.y;
    const int warp = threadIdx.x >> 5;
    const int lane = threadIdx.x & 31;
    const int sub  = blockIdx.x * 4 + warp;

    const int l0 = sub * SUBL;
    const int l1 = min(l0 + SUBL, LOUT);
    const int n  = l1 + KW - 1 - l0;     // tokens this sub-chunk (<= 24)

    const int* ids = tokens + b * L;
    int myid = 0;
    if (lane < n) myid = __ldg(ids + l0 + lane);

    const uint4* __restrict__ Kt16 = reinterpret_cast<const uint4*>(g_Kt); // 80/row
    const uint2* __restrict__ Kt8  = reinterpret_cast<const uint2*>(g_Kt); // 160/row

    float4 acc[5];
    #pragma unroll
    for (int i = 0; i < 5; i++) acc[i] = make_float4(0.f, 0.f, 0.f, 0.f);
    float4 vmax = make_float4(0.f, 0.f, 0.f, 0.f);   // relu: floor at 0

    #pragma unroll
    for (int j = 0; j < SUBL + KW - 1; j++) {       // j = p - l0
        if (j < n) {
            int id = __shfl_sync(0xFFFFFFFFu, myid, j);
            const uint4 A = __ldg(Kt16 + (size_t)id * 80 + lane);       // w0|w1, quad l
            const uint4 B = __ldg(Kt16 + (size_t)id * 80 + 32 + lane);  // w2|w3, quad l
            const uint2 C = __ldg(Kt8  + (size_t)id * 160 + 128 + lane);// w4,    quad l
            const uint2 v0 = make_uint2(A.x, A.y);
            const uint2 v1 = make_uint2(A.z, A.w);
            const uint2 v2 = make_uint2(B.x, B.y);
            const uint2 v3 = make_uint2(B.z, B.w);
            const uint2 v4 = C;
            // conv[l = p - w] += K[:, id, w]; slot(l) = (l - l0) mod 5
            addh4(acc[(j + 5 - 0) % 5], v0);
            addh4(acc[(j + 5 - 1) % 5], v1);
            addh4(acc[(j + 5 - 2) % 5], v2);
            addh4(acc[(j + 5 - 3) % 5], v3);
            addh4(acc[(j + 5 - 4) % 5], v4);
            // slot (j+1)%5: completed conv[p-4] when j>=4; stale boundary
            // pollution when j<4 — reset it either way.
            const int s = (j + 1) % 5;
            if (j >= 4) max4(vmax, acc[s]);
            acc[s] = make_float4(0.f, 0.f, 0.f, 0.f);
        }
    }
    float4* dst = reinterpret_cast<float4*>(&g_partial[b][sub][0]);
    dst[lane] = vmax;
}

// ---------------------------------------------------------------------------
// Kernel 3: reduce sub-chunk maxima + tiny FC.  grid = 32 (b), block = 256.
// Two thread-groups each scan half of NSUB, smem-max combine, shuffle FC.
// ---------------------------------------------------------------------------
__global__ void __launch_bounds__(256) final_kernel(const float* __restrict__ fc1_w,
                                                    const float* __restrict__ fc1_b,
                                                    float* __restrict__ out) {
    const int b   = blockIdx.x;
    const int t   = threadIdx.x;
    const int oc  = t & 127;             // oc index
    const int grp = t >> 7;              // 0 or 1: which NSUB half

    __shared__ float shmax[2][128];

    const float* part = &g_partial[b][0][0]; // [NSUB][128]
    float pooled = 0.f;
    #pragma unroll 8
    for (int s = grp * (NSUB / 2); s < (grp + 1) * (NSUB / 2); s++)
        pooled = fmaxf(pooled, part[s * OC + oc]);
    shmax[grp][oc] = pooled;
    __syncthreads();

    if (grp == 0) {
        pooled = fmaxf(shmax[0][oc], shmax[1][oc]);

        const int warp = oc >> 5, lane = oc & 31;
        __shared__ float shw[4][4];      // [warp][tc]
        #pragma unroll
        for (int tc = 0; tc < 4; tc++) {
            float v = pooled * fc1_w[tc * OC + oc];
            #pragma unroll
            for (int off = 16; off > 0; off >>= 1)
                v += __shfl_down_sync(0xFFFFFFFFu, v, off);
            if (lane == 0) shw[warp][tc] = v;
        }
        __syncthreads();
        if (oc < 4) {
            float s = shw[0][oc] + shw[1][oc] + shw[2][oc] + shw[3][oc];
            out[b * 4 + oc] = s + fc1_b[oc];
        }
    }
}

// ---------------------------------------------------------------------------
extern "C" void kernel_launch(void* const* d_in, const int* in_sizes, int n_in,
                              void* d_out, int out_size) {
    const int*   tokens = (const int*)  d_in[0];
    const float* k1     = (const float*)d_in[1];
    const float* fc1w   = (const float*)d_in[2];
    const float* fc1b   = (const float*)d_in[3];
    float*       out    = (float*)d_out;

    transpose_kernel<<<(CW + 63) / 64, 256>>>(k1);        // 2344 blocks

    conv_kernel<<<dim3(NSUB / 4, BATCH), 128>>>(tokens);  // (32, 32)

    final_kernel<<<BATCH, 256>>>(fc1w, fc1b, out);
}

// round 15
// speedup vs baseline: 1.2327x; 1.2327x over previous
#include <cuda_runtime.h>
#include <cuda_fp16.h>

// Problem constants
#define VSZ   30000
#define OC    128
#define KW    5
#define BATCH 32

constexpr int L    = 2560;          // 40*64 flattened token positions per batch
constexpr int LOUT = L - KW + 1;    // 2556
constexpr int CW   = VSZ * KW;      // 150000 columns (v*5+w)
constexpr int NSUB = 128;           // sub-chunks of the l-range
constexpr int SUBL = 20;            // 128*20 = 2560 >= LOUT

// Scratch: transposed fp16 table Kt[v][w][oc]  (38.4 MB, L2-resident)
__device__ __align__(16) __half g_Kt[(size_t)VSZ * KW * OC];
// Per-warp partial maxima: [b][sub][oc]
__device__ float g_partial[BATCH][NSUB][OC];

// ---------------------------------------------------------------------------
// Kernel 1: transpose + fp32->fp16 convert (R8 winner — at mixed-stream
// DRAM ceiling; 5 structural variants since all measured >= this).
// K is (128 x 150000), row = oc, col = v*5+w.  ->  Kt[col][oc] as half.
// Block = 64 columns x 128 oc rows, 256 threads, 4 passes; float4 loads,
// conflict-free uint tile, coalesced 256B Kt-row write-out.
// ---------------------------------------------------------------------------
__global__ void __launch_bounds__(256) transpose_kernel(const float* __restrict__ src) {
    __shared__ unsigned tile[64][65];         // [col-local][oc-pair 0..63]
    const int t     = threadIdx.x;
    const int rp0   = t >> 4;                 // 0..15
    const int c4    = (t & 15) * 4;           // column group within tile
    const int cbase = blockIdx.x * 64;
    const int c     = cbase + c4;
    const bool cok  = (c + 3 < CW);           // whole float4 in range (CW%4==0)

    #pragma unroll
    for (int i = 0; i < 4; i++) {
        const int RP = rp0 + 16 * i;          // rowpair 0..63 -> rows 2RP, 2RP+1
        if (cok) {
            const float4 fa = __ldcs(reinterpret_cast<const float4*>(
                                  src + (size_t)(2 * RP)     * CW + c));
            const float4 fb = __ldcs(reinterpret_cast<const float4*>(
                                  src + (size_t)(2 * RP + 1) * CW + c));
            half2 h0 = __floats2half2_rn(fa.x, fb.x);
            half2 h1 = __floats2half2_rn(fa.y, fb.y);
            half2 h2 = __floats2half2_rn(fa.z, fb.z);
            half2 h3 = __floats2half2_rn(fa.w, fb.w);
            tile[c4 + 0][RP] = *reinterpret_cast<unsigned*>(&h0);
            tile[c4 + 1][RP] = *reinterpret_cast<unsigned*>(&h1);
            tile[c4 + 2][RP] = *reinterpret_cast<unsigned*>(&h2);
            tile[c4 + 3][RP] = *reinterpret_cast<unsigned*>(&h3);
        }
    }
    __syncthreads();

    // Write out: 64 Kt rows x 64 uints (128 halfs) each.
    const int colu   = t & 63;                // uint (rowpair) index in Kt row
    const int rowsel = t >> 6;                // 0..3
    #pragma unroll
    for (int i = 0; i < 16; i++) {
        int row = rowsel + i * 4;             // col-local 0..63
        int vw  = cbase + row;
        if (vw < CW)
            reinterpret_cast<unsigned*>(g_Kt)[(size_t)vw * 64 + colu] = tile[row][colu];
    }
}

// ---------------------------------------------------------------------------
// Kernel 2: gather + sliding-window conv + relu-max (R10 winner).
// grid = (NSUB/4, BATCH), 128-thr blocks (1024 blocks = 6.92/SM smooths the
// SM-load quantization tail); one warp per sub-chunk; lane owns 4 oc as one
// uint2 -> 5 x 256B L2 sectors per token (sector count is what binds — R13
// showed fewer request instructions at equal sectors is a regression).
// fp32 accumulate (R11: fp16 accum perf-neutral, 3x worse error).
// Ids preloaded lane-parallel + __shfl.
// Ring-slot reset MUST be unconditional (boundary-pollution flush, see R3).
// ---------------------------------------------------------------------------
__device__ __forceinline__ void addh4(float4& a, const uint2 v) {
    const half2 h0 = *reinterpret_cast<const half2*>(&v.x);
    const half2 h1 = *reinterpret_cast<const half2*>(&v.y);
    float2 f0 = __half22float2(h0);
    float2 f1 = __half22float2(h1);
    a.x += f0.x; a.y += f0.y; a.z += f1.x; a.w += f1.y;
}
__device__ __forceinline__ void max4(float4& a, const float4 b) {
    a.x = fmaxf(a.x, b.x); a.y = fmaxf(a.y, b.y);
    a.z = fmaxf(a.z, b.z); a.w = fmaxf(a.w, b.w);
}

__global__ void __launch_bounds__(128) conv_kernel(const int* __restrict__ tokens) {
    const int b    = blockIdx.y;
    const int warp = threadIdx.x >> 5;
    const int lane = threadIdx.x & 31;
    const int sub  = blockIdx.x * 4 + warp;

    const int l0 = sub * SUBL;
    const int l1 = min(l0 + SUBL, LOUT);
    const int n  = l1 + KW - 1 - l0;     // tokens this sub-chunk (<= 24)

    const int* ids = tokens + b * L;
    int myid = 0;
    if (lane < n) myid = __ldg(ids + l0 + lane);

    const uint2* __restrict__ Kt8 = reinterpret_cast<const uint2*>(g_Kt);

    float4 acc[5];
    #pragma unroll
    for (int i = 0; i < 5; i++) acc[i] = make_float4(0.f, 0.f, 0.f, 0.f);
    float4 vmax = make_float4(0.f, 0.f, 0.f, 0.f);   // relu: floor at 0

    #pragma unroll
    for (int j = 0; j < SUBL + KW - 1; j++) {       // j = p - l0
        if (j < n) {
            int id = __shfl_sync(0xFFFFFFFFu, myid, j);
            // 640 halfs per token row = 160 uint2; w-row = 32 uint2.
            const uint2* srcp = Kt8 + (size_t)id * 160 + lane;
            uint2 v0 = __ldg(srcp +   0);
            uint2 v1 = __ldg(srcp +  32);
            uint2 v2 = __ldg(srcp +  64);
            uint2 v3 = __ldg(srcp +  96);
            uint2 v4 = __ldg(srcp + 128);
            // conv[l = p - w] += K[:, id, w]; slot(l) = (l - l0) mod 5
            addh4(acc[(j + 5 - 0) % 5], v0);
            addh4(acc[(j + 5 - 1) % 5], v1);
            addh4(acc[(j + 5 - 2) % 5], v2);
            addh4(acc[(j + 5 - 3) % 5], v3);
            addh4(acc[(j + 5 - 4) % 5], v4);
            // slot (j+1)%5: completed conv[p-4] when j>=4; stale boundary
            // pollution when j<4 — reset it either way.
            const int s = (j + 1) % 5;
            if (j >= 4) max4(vmax, acc[s]);
            acc[s] = make_float4(0.f, 0.f, 0.f, 0.f);
        }
    }
    float4* dst = reinterpret_cast<float4*>(&g_partial[b][sub][0]);
    dst[lane] = vmax;
}

// ---------------------------------------------------------------------------
// Kernel 3: reduce sub-chunk maxima + tiny FC.  grid = 32 (b), block = 256.
// Two thread-groups each scan half of NSUB, smem-max combine, shuffle FC.
// ---------------------------------------------------------------------------
__global__ void __launch_bounds__(256) final_kernel(const float* __restrict__ fc1_w,
                                                    const float* __restrict__ fc1_b,
                                                    float* __restrict__ out) {
    const int b   = blockIdx.x;
    const int t   = threadIdx.x;
    const int oc  = t & 127;             // oc index
    const int grp = t >> 7;              // 0 or 1: which NSUB half

    __shared__ float shmax[2][128];

    const float* part = &g_partial[b][0][0]; // [NSUB][128]
    float pooled = 0.f;
    #pragma unroll 8
    for (int s = grp * (NSUB / 2); s < (grp + 1) * (NSUB / 2); s++)
        pooled = fmaxf(pooled, part[s * OC + oc]);
    shmax[grp][oc] = pooled;
    __syncthreads();

    if (grp == 0) {
        pooled = fmaxf(shmax[0][oc], shmax[1][oc]);

        const int warp = oc >> 5, lane = oc & 31;
        __shared__ float shw[4][4];      // [warp][tc]
        #pragma unroll
        for (int tc = 0; tc < 4; tc++) {
            float v = pooled * fc1_w[tc * OC + oc];
            #pragma unroll
            for (int off = 16; off > 0; off >>= 1)
                v += __shfl_down_sync(0xFFFFFFFFu, v, off);
            if (lane == 0) shw[warp][tc] = v;
        }
        __syncthreads();
        if (oc < 4) {
            float s = shw[0][oc] + shw[1][oc] + shw[2][oc] + shw[3][oc];
            out[b * 4 + oc] = s + fc1_b[oc];
        }
    }
}

// ---------------------------------------------------------------------------
extern "C" void kernel_launch(void* const* d_in, const int* in_sizes, int n_in,
                              void* d_out, int out_size) {
    const int*   tokens = (const int*)  d_in[0];
    const float* k1     = (const float*)d_in[1];
    const float* fc1w   = (const float*)d_in[2];
    const float* fc1b   = (const float*)d_in[3];
    float*       out    = (float*)d_out;

    transpose_kernel<<<(CW + 63) / 64, 256>>>(k1);        // 2344 blocks

    conv_kernel<<<dim3(NSUB / 4, BATCH), 128>>>(tokens);  // (32, 32) = 1024 blocks

    final_kernel<<<BATCH, 256>>>(fc1w, fc1b, out);
}